// round 2
// baseline (speedup 1.0000x reference)
#include <cuda_runtime.h>
#include <math.h>

#define Bq 256
#define Hq 128
#define Nq 2048
#define KK 256   // effective K after folding decoder into bias
#define BM 128
#define BN 128
#define BK 32

// per-batch bias: c[b][h] = sum_k W[h][256+k] * dec[b][k]
__device__ float g_bias[Bq * Hq];

// ---------------------------------------------------------------------------
// Kernel 0: bias  c[b,h] = W3 @ dec[b]
// grid: (256), block: (128) = 4 warps; each warp owns 32 h rows.
// ---------------------------------------------------------------------------
__global__ void bias_kernel(const float* __restrict__ dec,
                            const float* __restrict__ W) {
    __shared__ float dsh[Hq];
    const int b = blockIdx.x;
    const int t = threadIdx.x;
    const int lane = t & 31;
    const int w = t >> 5;

    dsh[t] = dec[b * Hq + t];
    __syncthreads();

    for (int h = w * 32; h < w * 32 + 32; h++) {
        float p = 0.f;
#pragma unroll
        for (int i = 0; i < 4; i++) {
            int k = lane + 32 * i;
            p = fmaf(W[h * 384 + 256 + k], dsh[k], p);  // coalesced along k
        }
#pragma unroll
        for (int off = 16; off; off >>= 1)
            p += __shfl_xor_sync(0xffffffffu, p, off);
        if (lane == 0) g_bias[b * Hq + h] = p;
    }
}

// ---------------------------------------------------------------------------
// Kernel 1: fused GEMM + tanh + v-dot  -> raw scores in d_out [B, N]
//   C[h,n] = sum_k W[h,k] * H[k,n],  H rows 0..127 = static, 128..255 = dynamic
//   score[n] = sum_h v[h] * tanh(C[h,n] + c[b,h])
// grid: (N/BN=16, B=256), block: 256 threads (16x16), 8x8 register tile
// with split 4+4 fragments for conflict-free LDS.128.
// ---------------------------------------------------------------------------
__global__ __launch_bounds__(256) void score_kernel(
    const float* __restrict__ st, const float* __restrict__ dy,
    const float* __restrict__ v, const float* __restrict__ W,
    float* __restrict__ out) {
    __shared__ float As[BK][BM];      // W tile, transposed: As[k][h]
    __shared__ float Bs[BK][BN];      // hidden tile: Bs[k][n]
    __shared__ float vs[Hq];
    __shared__ float cs[Hq];
    __shared__ float red[16][BN];

    const int b  = blockIdx.y;
    const int n0 = blockIdx.x * BN;
    const int t  = threadIdx.x;
    const int tx = t & 15;
    const int ty = t >> 4;

    if (t < Hq) {
        vs[t] = v[t];
        cs[t] = g_bias[b * Hq + t];
    }

    float acc[8][8];
#pragma unroll
    for (int i = 0; i < 8; i++)
#pragma unroll
        for (int j = 0; j < 8; j++) acc[i][j] = 0.f;

    const float* base_st = st + (size_t)b * Hq * Nq;
    const float* base_dy = dy + (size_t)b * Hq * Nq;

    for (int k0 = 0; k0 < KK; k0 += BK) {
        // --- load A tile: W[h][k0..k0+32), store transposed As[k][h] ---
#pragma unroll
        for (int i = 0; i < 4; i++) {
            int idx = t + 256 * i;            // 0..1023 float4 slots
            int h   = idx >> 3;               // 0..127
            int c4  = idx & 7;                // 0..7
            float4 wv = *(const float4*)&W[h * 384 + k0 + c4 * 4];
            As[c4 * 4 + 0][h] = wv.x;
            As[c4 * 4 + 1][h] = wv.y;
            As[c4 * 4 + 2][h] = wv.z;
            As[c4 * 4 + 3][h] = wv.w;
        }
        // --- load B tile: hidden[k0+row][n0 + ...], coalesced float4 ---
#pragma unroll
        for (int i = 0; i < 4; i++) {
            int idx = t + 256 * i;
            int row = idx >> 5;               // 0..31
            int c4  = idx & 31;               // 0..31
            int gk  = k0 + row;
            const float* src = (gk < Hq) ? (base_st + (size_t)gk * Nq)
                                         : (base_dy + (size_t)(gk - Hq) * Nq);
            *(float4*)&Bs[row][c4 * 4] = *(const float4*)&src[n0 + c4 * 4];
        }
        __syncthreads();

#pragma unroll
        for (int k = 0; k < BK; k++) {
            float4 a0 = *(const float4*)&As[k][ty * 4];
            float4 a1 = *(const float4*)&As[k][ty * 4 + 64];
            float4 b0 = *(const float4*)&Bs[k][tx * 4];
            float4 b1 = *(const float4*)&Bs[k][tx * 4 + 64];
            float af[8] = {a0.x, a0.y, a0.z, a0.w, a1.x, a1.y, a1.z, a1.w};
            float bf[8] = {b0.x, b0.y, b0.z, b0.w, b1.x, b1.y, b1.z, b1.w};
#pragma unroll
            for (int i = 0; i < 8; i++)
#pragma unroll
                for (int j = 0; j < 8; j++)
                    acc[i][j] = fmaf(af[i], bf[j], acc[i][j]);
        }
        __syncthreads();
    }

    // --- epilogue: tanh(acc + c[h]), dot with v[h], partial per n ---
    float part[8] = {0.f, 0.f, 0.f, 0.f, 0.f, 0.f, 0.f, 0.f};
#pragma unroll
    for (int i = 0; i < 8; i++) {
        int h = (i < 4) ? (ty * 4 + i) : (64 + ty * 4 + (i - 4));
        float vh = vs[h];
        float ch = cs[h];
#pragma unroll
        for (int j = 0; j < 8; j++) {
            float x  = acc[i][j] + ch;
            float th = tanhf(x);
            part[j] = fmaf(vh, th, part[j]);
        }
    }
    *(float4*)&red[ty][tx * 4]      = make_float4(part[0], part[1], part[2], part[3]);
    *(float4*)&red[ty][tx * 4 + 64] = make_float4(part[4], part[5], part[6], part[7]);
    __syncthreads();

    if (t < BN) {
        float s = 0.f;
#pragma unroll
        for (int r = 0; r < 16; r++) s += red[r][t];
        out[(size_t)b * Nq + n0 + t] = s;
    }
}

// ---------------------------------------------------------------------------
// Kernel 2: in-place row softmax over N=2048. grid (256), block (256).
// ---------------------------------------------------------------------------
__global__ __launch_bounds__(256) void softmax_kernel(float* __restrict__ out) {
    __shared__ float sm[256];
    const int b = blockIdx.x;
    const int t = threadIdx.x;
    float* row = out + (size_t)b * Nq;

    float vals[8];
    float m = -1e30f;
#pragma unroll
    for (int i = 0; i < 8; i++) {
        vals[i] = row[t + 256 * i];
        m = fmaxf(m, vals[i]);
    }
    sm[t] = m;
    __syncthreads();
    for (int s = 128; s > 0; s >>= 1) {
        if (t < s) sm[t] = fmaxf(sm[t], sm[t + s]);
        __syncthreads();
    }
    const float M = sm[0];
    __syncthreads();

    float sum = 0.f;
#pragma unroll
    for (int i = 0; i < 8; i++) {
        vals[i] = __expf(vals[i] - M);
        sum += vals[i];
    }
    sm[t] = sum;
    __syncthreads();
    for (int s = 128; s > 0; s >>= 1) {
        if (t < s) sm[t] += sm[t + s];
        __syncthreads();
    }
    const float inv = 1.f / sm[0];
#pragma unroll
    for (int i = 0; i < 8; i++) row[t + 256 * i] = vals[i] * inv;
}

// ---------------------------------------------------------------------------
extern "C" void kernel_launch(void* const* d_in, const int* in_sizes, int n_in,
                              void* d_out, int out_size) {
    const float* st  = (const float*)d_in[0];  // static_hidden  [B,H,N]
    const float* dy  = (const float*)d_in[1];  // dynamic_hidden [B,H,N]
    const float* dec = (const float*)d_in[2];  // decoder_hidden [B,H]
    const float* v   = (const float*)d_in[3];  // v [1,1,H]
    const float* W   = (const float*)d_in[4];  // W [1,H,3H]
    float* out = (float*)d_out;                // [B,1,N]

    bias_kernel<<<Bq, Hq>>>(dec, W);
    dim3 grid(Nq / BN, Bq);
    score_kernel<<<grid, 256>>>(st, dy, v, W, out);
    softmax_kernel<<<Bq, 256>>>(out);
}

// round 4
// speedup vs baseline: 3.2492x; 3.2492x over previous
#include <cuda_runtime.h>
#include <math.h>
#include <stdint.h>

#define Bq 256
#define Hq 128
#define Nq 2048
#define KK 256          // effective K (decoder folded into bias)
#define BM 128
#define BN 128
#define BK 32
#define ASTRIDE 36      // As[m][k] pad: bank(4*gid+tig) all-distinct
#define BSTRIDE 136     // Bs[k][n] pad: bank(8*tig+gid) all-distinct

__device__ float g_bias[Bq * Hq];

// ---------------- helpers ----------------
__device__ __forceinline__ float to_tf32(float x) {
    float y; asm("cvt.rna.tf32.f32 %0, %1;" : "=f"(y) : "f"(x)); return y;
}
__device__ __forceinline__ float tanh_fast(float x) {
    float y; asm("tanh.approx.f32 %0, %1;" : "=f"(y) : "f"(x)); return y;
}
__device__ __forceinline__ void mma8(float* c, const uint32_t* a, const uint32_t* b) {
    asm volatile(
        "mma.sync.aligned.m16n8k8.row.col.f32.tf32.tf32.f32 "
        "{%0,%1,%2,%3}, {%4,%5,%6,%7}, {%8,%9}, {%0,%1,%2,%3};"
        : "+f"(c[0]), "+f"(c[1]), "+f"(c[2]), "+f"(c[3])
        : "r"(a[0]), "r"(a[1]), "r"(a[2]), "r"(a[3]), "r"(b[0]), "r"(b[1]));
}

// ---------------------------------------------------------------------------
// Kernel 0: bias  c[b,h] = W3 @ dec[b]
// ---------------------------------------------------------------------------
__global__ void bias_kernel(const float* __restrict__ dec,
                            const float* __restrict__ W) {
    __shared__ float dsh[Hq];
    const int b = blockIdx.x, t = threadIdx.x;
    const int lane = t & 31, w = t >> 5;
    dsh[t] = dec[b * Hq + t];
    __syncthreads();
    for (int h = w * 32; h < w * 32 + 32; h++) {
        float p = 0.f;
#pragma unroll
        for (int i = 0; i < 4; i++)
            p = fmaf(W[h * 384 + 256 + lane + 32 * i], dsh[lane + 32 * i], p);
#pragma unroll
        for (int off = 16; off; off >>= 1)
            p += __shfl_xor_sync(0xffffffffu, p, off);
        if (lane == 0) g_bias[b * Hq + h] = p;
    }
}

// ---------------------------------------------------------------------------
// Kernel 1: HMMA tf32 GEMM + fused tanh/v-dot -> raw scores
//   D[h,n] = W[h,k] @ hidden[k,n];  score[n] = sum_h v[h]*tanh(D+bias)
// grid (16, 256), 256 threads (8 warps, 4x2 warp grid, 32x64 warp tile)
// ---------------------------------------------------------------------------
__global__ __launch_bounds__(256, 2) void score_kernel(
    const float* __restrict__ st, const float* __restrict__ dy,
    const float* __restrict__ v, const float* __restrict__ W,
    float* __restrict__ out) {
    __shared__ __align__(16) float As[BM][ASTRIDE];   // W tile [m][k]
    __shared__ __align__(16) float Bs[BK][BSTRIDE];   // hidden tile [k][n]
    __shared__ float vs[Hq];
    __shared__ float cs[Hq];
    __shared__ float red[4][BN];

    const int b  = blockIdx.y;
    const int n0 = blockIdx.x * BN;
    const int t  = threadIdx.x;
    const int w  = t >> 5;
    const int lane = t & 31;
    const int wm = w & 3;          // 0..3 : m-block of 32
    const int wn = w >> 2;         // 0..1 : n-block of 64
    const int gid = lane >> 2;     // 0..7
    const int tig = lane & 3;      // 0..3

    if (t < Hq) {
        vs[t] = v[t];
        cs[t] = g_bias[b * Hq + t];
    }

    float acc[2][8][4];
#pragma unroll
    for (int i = 0; i < 2; i++)
#pragma unroll
        for (int j = 0; j < 8; j++)
#pragma unroll
            for (int q = 0; q < 4; q++) acc[i][j][q] = 0.f;

    const float* base_st = st + (size_t)b * Hq * Nq;
    const float* base_dy = dy + (size_t)b * Hq * Nq;

    for (int k0 = 0; k0 < KK; k0 += BK) {
        // --- A tile: W[h][k0..k0+32) -> As[h][k], tf32-rounded ---
#pragma unroll
        for (int i = 0; i < 4; i++) {
            int idx = t + 256 * i;            // 1024 float4 slots
            int h   = idx >> 3;               // 0..127
            int c4  = idx & 7;                // 0..7
            float4 wv = *(const float4*)&W[h * 384 + k0 + c4 * 4];
            wv.x = to_tf32(wv.x); wv.y = to_tf32(wv.y);
            wv.z = to_tf32(wv.z); wv.w = to_tf32(wv.w);
            *(float4*)&As[h][c4 * 4] = wv;
        }
        // --- B tile: hidden[k0+row][n0..n0+128) -> Bs[row][n], tf32 ---
#pragma unroll
        for (int i = 0; i < 4; i++) {
            int idx = t + 256 * i;
            int row = idx >> 5;               // 0..31
            int c4  = idx & 31;               // 0..31
            int gk  = k0 + row;
            const float* src = (gk < Hq) ? (base_st + (size_t)gk * Nq)
                                         : (base_dy + (size_t)(gk - Hq) * Nq);
            float4 hv = *(const float4*)&src[n0 + c4 * 4];
            hv.x = to_tf32(hv.x); hv.y = to_tf32(hv.y);
            hv.z = to_tf32(hv.z); hv.w = to_tf32(hv.w);
            *(float4*)&Bs[row][c4 * 4] = hv;
        }
        __syncthreads();

#pragma unroll
        for (int kf = 0; kf < 4; kf++) {
            const int k = kf * 8;
            uint32_t a[2][4], bb[8][2];
#pragma unroll
            for (int mf = 0; mf < 2; mf++) {
                const int m = wm * 32 + mf * 16;
                a[mf][0] = __float_as_uint(As[m + gid][k + tig]);
                a[mf][1] = __float_as_uint(As[m + gid + 8][k + tig]);
                a[mf][2] = __float_as_uint(As[m + gid][k + tig + 4]);
                a[mf][3] = __float_as_uint(As[m + gid + 8][k + tig + 4]);
            }
#pragma unroll
            for (int nf = 0; nf < 8; nf++) {
                const int n = wn * 64 + nf * 8;
                bb[nf][0] = __float_as_uint(Bs[k + tig][n + gid]);
                bb[nf][1] = __float_as_uint(Bs[k + tig + 4][n + gid]);
            }
#pragma unroll
            for (int mf = 0; mf < 2; mf++)
#pragma unroll
                for (int nf = 0; nf < 8; nf++)
                    mma8(acc[mf][nf], a[mf], bb[nf]);
        }
        __syncthreads();
    }

    // --- epilogue: tanh + v-dot, reduce over m ---
    // thread's rows: wm*32 + mf*16 + {gid, gid+8}; cols: wn*64 + nf*8 + 2tig+{0,1}
#pragma unroll
    for (int nf = 0; nf < 8; nf++) {
        float p0 = 0.f, p1 = 0.f;
#pragma unroll
        for (int mf = 0; mf < 2; mf++) {
            const int r0 = wm * 32 + mf * 16 + gid;
            const int r1 = r0 + 8;
            const float v0 = vs[r0], c0 = cs[r0];
            const float v1 = vs[r1], c1 = cs[r1];
            p0 = fmaf(v0, tanh_fast(acc[mf][nf][0] + c0), p0);
            p1 = fmaf(v0, tanh_fast(acc[mf][nf][1] + c0), p1);
            p0 = fmaf(v1, tanh_fast(acc[mf][nf][2] + c1), p0);
            p1 = fmaf(v1, tanh_fast(acc[mf][nf][3] + c1), p1);
        }
        // reduce across gid (lanes differing in bits 2..4)
#pragma unroll
        for (int off = 4; off < 32; off <<= 1) {
            p0 += __shfl_xor_sync(0xffffffffu, p0, off);
            p1 += __shfl_xor_sync(0xffffffffu, p1, off);
        }
        if (gid == 0) {
            const int col = wn * 64 + nf * 8 + 2 * tig;
            red[wm][col]     = p0;
            red[wm][col + 1] = p1;
        }
    }
    __syncthreads();

    if (t < BN)
        out[(size_t)b * Nq + n0 + t] =
            red[0][t] + red[1][t] + red[2][t] + red[3][t];
}

// ---------------------------------------------------------------------------
// Kernel 2: in-place row softmax over N=2048
// ---------------------------------------------------------------------------
__global__ __launch_bounds__(256) void softmax_kernel(float* __restrict__ out) {
    __shared__ float sm[256];
    const int b = blockIdx.x, t = threadIdx.x;
    float* row = out + (size_t)b * Nq;
    float vals[8];
    float m = -1e30f;
#pragma unroll
    for (int i = 0; i < 8; i++) { vals[i] = row[t + 256 * i]; m = fmaxf(m, vals[i]); }
    sm[t] = m;
    __syncthreads();
    for (int s = 128; s > 0; s >>= 1) {
        if (t < s) sm[t] = fmaxf(sm[t], sm[t + s]);
        __syncthreads();
    }
    const float M = sm[0];
    __syncthreads();
    float sum = 0.f;
#pragma unroll
    for (int i = 0; i < 8; i++) { vals[i] = __expf(vals[i] - M); sum += vals[i]; }
    sm[t] = sum;
    __syncthreads();
    for (int s = 128; s > 0; s >>= 1) {
        if (t < s) sm[t] += sm[t + s];
        __syncthreads();
    }
    const float inv = 1.f / sm[0];
#pragma unroll
    for (int i = 0; i < 8; i++) row[t + 256 * i] = vals[i] * inv;
}

// ---------------------------------------------------------------------------
extern "C" void kernel_launch(void* const* d_in, const int* in_sizes, int n_in,
                              void* d_out, int out_size) {
    const float* st  = (const float*)d_in[0];  // static_hidden  [B,H,N]
    const float* dy  = (const float*)d_in[1];  // dynamic_hidden [B,H,N]
    const float* dec = (const float*)d_in[2];  // decoder_hidden [B,H]
    const float* v   = (const float*)d_in[3];  // v [1,1,H]
    const float* W   = (const float*)d_in[4];  // W [1,H,3H]
    float* out = (float*)d_out;                // [B,1,N]

    bias_kernel<<<Bq, Hq>>>(dec, W);
    score_kernel<<<dim3(Nq / BN, Bq), 256>>>(st, dy, v, W, out);
    softmax_kernel<<<Bq, 256>>>(out);
}

// round 5
// speedup vs baseline: 4.5009x; 1.3852x over previous
#include <cuda_runtime.h>
#include <cuda_fp16.h>
#include <math.h>
#include <stdint.h>

#define Bq 256
#define Hq 128
#define Nq 2048
#define KK 256          // effective K (decoder folded into bias)
#define BM 128
#define BN 128
#define BK 32
#define AS2 20          // As16[h][k2] stride in half2 (LDS banks gid*20+tig distinct)
#define BS2 136         // Bs16[k2][n] stride in half2 (LDS banks 8*tig+gid distinct)

// ---------------- helpers ----------------
__device__ __forceinline__ float tanh_fast(float x) {
    float y; asm("tanh.approx.f32 %0, %1;" : "=f"(y) : "f"(x)); return y;
}
__device__ __forceinline__ void mma16(float* c, const uint32_t* a, const uint32_t* b) {
    asm volatile(
        "mma.sync.aligned.m16n8k16.row.col.f32.f16.f16.f32 "
        "{%0,%1,%2,%3}, {%4,%5,%6,%7}, {%8,%9}, {%0,%1,%2,%3};"
        : "+f"(c[0]), "+f"(c[1]), "+f"(c[2]), "+f"(c[3])
        : "r"(a[0]), "r"(a[1]), "r"(a[2]), "r"(a[3]), "r"(b[0]), "r"(b[1]));
}
__device__ __forceinline__ uint32_t pack2(float lo, float hi) {
    uint32_t r;
    asm("cvt.rn.f16x2.f32 %0, %2, %1;" : "=r"(r) : "f"(lo), "f"(hi));
    return r;  // lo in low half, hi in high half
}

// ---------------------------------------------------------------------------
// Kernel 1: fp16 HMMA GEMM + fused bias + tanh/v-dot -> raw scores
//   D[h,n] = W[h,0:256] @ [static;dynamic](k,n);  bias[h] = W[h,256:384]@dec
//   score[n] = sum_h v[h] * tanh(D[h,n] + bias[h])
// grid (16, 256), 256 threads (8 warps, 4x2 warp grid, 32x64 warp tiles)
// ---------------------------------------------------------------------------
__global__ __launch_bounds__(256, 2) void score_kernel(
    const float* __restrict__ st, const float* __restrict__ dy,
    const float* __restrict__ dec, const float* __restrict__ v,
    const float* __restrict__ W, float* __restrict__ out) {
    __shared__ __align__(16) __half2 As16[BM][AS2];   // W tile, k-packed
    __shared__ __align__(16) __half2 Bs16[BK / 2][BS2];
    __shared__ float vs[Hq];
    __shared__ float cs[Hq];
    __shared__ float red[4][BN];   // also used as dec staging before main loop

    const int b  = blockIdx.y;
    const int n0 = blockIdx.x * BN;
    const int t  = threadIdx.x;
    const int w  = t >> 5;
    const int lane = t & 31;
    const int wm = w & 3;          // m-block of 32
    const int wn = w >> 2;         // n-block of 64
    const int gid = lane >> 2;     // 0..7
    const int tig = lane & 3;      // 0..3

    // ---- fused bias: cs[h] = W[h][256:384] . dec[b]  (warp w -> 16 rows) ----
    if (t < Hq) {
        vs[t] = v[t];
        red[0][t] = dec[b * Hq + t];
    }
    __syncthreads();
    {
        const float* dsh = &red[0][0];
#pragma unroll
        for (int r = 0; r < 16; r++) {
            const int h = w * 16 + r;
            float p = 0.f;
#pragma unroll
            for (int i = 0; i < 4; i++)
                p = fmaf(W[h * 384 + 256 + lane + 32 * i], dsh[lane + 32 * i], p);
#pragma unroll
            for (int off = 16; off; off >>= 1)
                p += __shfl_xor_sync(0xffffffffu, p, off);
            if (lane == 0) cs[h] = p;
        }
    }
    __syncthreads();

    float acc[2][8][4];
#pragma unroll
    for (int i = 0; i < 2; i++)
#pragma unroll
        for (int j = 0; j < 8; j++)
#pragma unroll
            for (int q = 0; q < 4; q++) acc[i][j][q] = 0.f;

    const float* base_st = st + (size_t)b * Hq * Nq;
    const float* base_dy = dy + (size_t)b * Hq * Nq;

    for (int k0 = 0; k0 < KK; k0 += BK) {
        // --- A tile: W[h][k0..k0+32) -> As16[h][0..16) (k-packed half2) ---
#pragma unroll
        for (int i = 0; i < 2; i++) {
            int s = t + 256 * i;              // 512 slots
            int h = s >> 2;                   // 0..127
            int q = s & 3;                    // k-octet 0..3
            const float* wp = &W[h * 384 + k0 + q * 8];
            float4 w0 = *(const float4*)wp;
            float4 w1 = *(const float4*)(wp + 4);
            uint4 pk;
            pk.x = pack2(w0.x, w0.y);
            pk.y = pack2(w0.z, w0.w);
            pk.z = pack2(w1.x, w1.y);
            pk.w = pack2(w1.z, w1.w);
            *(uint4*)&As16[h][q * 4] = pk;
        }
        // --- B tile: rows k0+2k2, k0+2k2+1 -> Bs16[k2][n] (k-packed) ---
#pragma unroll
        for (int i = 0; i < 2; i++) {
            int s = t + 256 * i;              // 512 slots
            int k2 = s >> 5;                  // 0..15
            int c4 = s & 31;                  // n quad
            int gk = k0 + 2 * k2;
            const float* src = (gk < Hq) ? (base_st + (size_t)gk * Nq)
                                         : (base_dy + (size_t)(gk - Hq) * Nq);
            float4 r0 = *(const float4*)&src[n0 + c4 * 4];
            float4 r1 = *(const float4*)&src[n0 + c4 * 4 + Nq];
            uint4 pk;
            pk.x = pack2(r0.x, r1.x);
            pk.y = pack2(r0.y, r1.y);
            pk.z = pack2(r0.z, r1.z);
            pk.w = pack2(r0.w, r1.w);
            *(uint4*)&Bs16[k2][c4 * 4] = pk;
        }
        __syncthreads();

#pragma unroll
        for (int kf = 0; kf < 2; kf++) {
            const int k2 = kf * 8;
            uint32_t a[2][4], bb[8][2];
#pragma unroll
            for (int mf = 0; mf < 2; mf++) {
                const int m = wm * 32 + mf * 16;
                a[mf][0] = *(const uint32_t*)&As16[m + gid][k2 + tig];
                a[mf][1] = *(const uint32_t*)&As16[m + gid + 8][k2 + tig];
                a[mf][2] = *(const uint32_t*)&As16[m + gid][k2 + tig + 4];
                a[mf][3] = *(const uint32_t*)&As16[m + gid + 8][k2 + tig + 4];
            }
#pragma unroll
            for (int nf = 0; nf < 8; nf++) {
                const int n = wn * 64 + nf * 8;
                bb[nf][0] = *(const uint32_t*)&Bs16[k2 + tig][n + gid];
                bb[nf][1] = *(const uint32_t*)&Bs16[k2 + tig + 4][n + gid];
            }
#pragma unroll
            for (int mf = 0; mf < 2; mf++)
#pragma unroll
                for (int nf = 0; nf < 8; nf++)
                    mma16(acc[mf][nf], a[mf], bb[nf]);
        }
        __syncthreads();
    }

    // --- epilogue: tanh + v-dot, reduce over m ---
#pragma unroll
    for (int nf = 0; nf < 8; nf++) {
        float p0 = 0.f, p1 = 0.f;
#pragma unroll
        for (int mf = 0; mf < 2; mf++) {
            const int r0 = wm * 32 + mf * 16 + gid;
            const int r1 = r0 + 8;
            const float v0 = vs[r0], c0 = cs[r0];
            const float v1 = vs[r1], c1 = cs[r1];
            p0 = fmaf(v0, tanh_fast(acc[mf][nf][0] + c0), p0);
            p1 = fmaf(v0, tanh_fast(acc[mf][nf][1] + c0), p1);
            p0 = fmaf(v1, tanh_fast(acc[mf][nf][2] + c1), p0);
            p1 = fmaf(v1, tanh_fast(acc[mf][nf][3] + c1), p1);
        }
#pragma unroll
        for (int off = 4; off < 32; off <<= 1) {
            p0 += __shfl_xor_sync(0xffffffffu, p0, off);
            p1 += __shfl_xor_sync(0xffffffffu, p1, off);
        }
        if (gid == 0) {
            const int col = wn * 64 + nf * 8 + 2 * tig;
            red[wm][col]     = p0;
            red[wm][col + 1] = p1;
        }
    }
    __syncthreads();

    if (t < BN)
        out[(size_t)b * Nq + n0 + t] =
            red[0][t] + red[1][t] + red[2][t] + red[3][t];
}

// ---------------------------------------------------------------------------
// Kernel 2: in-place row softmax over N=2048 (shfl + cross-warp smem reduce)
// ---------------------------------------------------------------------------
__global__ __launch_bounds__(256) void softmax_kernel(float* __restrict__ out) {
    __shared__ float sm[8];
    const int b = blockIdx.x, t = threadIdx.x;
    const int w = t >> 5, lane = t & 31;
    float* row = out + (size_t)b * Nq;

    float vals[8];
    float m = -1e30f;
#pragma unroll
    for (int i = 0; i < 8; i++) { vals[i] = row[t + 256 * i]; m = fmaxf(m, vals[i]); }
#pragma unroll
    for (int off = 16; off; off >>= 1)
        m = fmaxf(m, __shfl_xor_sync(0xffffffffu, m, off));
    if (lane == 0) sm[w] = m;
    __syncthreads();
    float M = sm[lane & 7];
#pragma unroll
    for (int off = 4; off; off >>= 1)
        M = fmaxf(M, __shfl_xor_sync(0xffffffffu, M, off));

    float sum = 0.f;
#pragma unroll
    for (int i = 0; i < 8; i++) { vals[i] = __expf(vals[i] - M); sum += vals[i]; }
#pragma unroll
    for (int off = 16; off; off >>= 1)
        sum += __shfl_xor_sync(0xffffffffu, sum, off);
    __syncthreads();
    if (lane == 0) sm[w] = sum;
    __syncthreads();
    float S = sm[lane & 7];
#pragma unroll
    for (int off = 4; off; off >>= 1)
        S += __shfl_xor_sync(0xffffffffu, S, off);

    const float inv = 1.f / S;
#pragma unroll
    for (int i = 0; i < 8; i++) row[t + 256 * i] = vals[i] * inv;
}

// ---------------------------------------------------------------------------
extern "C" void kernel_launch(void* const* d_in, const int* in_sizes, int n_in,
                              void* d_out, int out_size) {
    const float* st  = (const float*)d_in[0];  // static_hidden  [B,H,N]
    const float* dy  = (const float*)d_in[1];  // dynamic_hidden [B,H,N]
    const float* dec = (const float*)d_in[2];  // decoder_hidden [B,H]
    const float* v   = (const float*)d_in[3];  // v [1,1,H]
    const float* W   = (const float*)d_in[4];  // W [1,H,3H]
    float* out = (float*)d_out;                // [B,1,N]

    score_kernel<<<dim3(Nq / BN, Bq), 256>>>(st, dy, dec, v, W, out);
    softmax_kernel<<<Bq, 256>>>(out);
}

// round 6
// speedup vs baseline: 5.0366x; 1.1190x over previous
#include <cuda_runtime.h>
#include <cuda_fp16.h>
#include <math.h>
#include <stdint.h>

#define Bq 256
#define Hq 128
#define Nq 2048
#define KK 256          // effective K (decoder folded into bias)
#define BM 128
#define BN 128
#define BK 32
#define AS2 20          // As16[h][k2] stride in half2
#define BS2 136         // Bs16[k2][n] stride in half2

// ---------------- helpers ----------------
__device__ __forceinline__ float tanh_fast(float x) {
    float y; asm("tanh.approx.f32 %0, %1;" : "=f"(y) : "f"(x)); return y;
}
__device__ __forceinline__ void mma16(float* c, const uint32_t* a, const uint32_t* b) {
    asm volatile(
        "mma.sync.aligned.m16n8k16.row.col.f32.f16.f16.f32 "
        "{%0,%1,%2,%3}, {%4,%5,%6,%7}, {%8,%9}, {%0,%1,%2,%3};"
        : "+f"(c[0]), "+f"(c[1]), "+f"(c[2]), "+f"(c[3])
        : "r"(a[0]), "r"(a[1]), "r"(a[2]), "r"(a[3]), "r"(b[0]), "r"(b[1]));
}
__device__ __forceinline__ uint32_t pack2(float lo, float hi) {
    uint32_t r;
    asm("cvt.rn.f16x2.f32 %0, %2, %1;" : "=r"(r) : "f"(lo), "f"(hi));
    return r;
}

// ---------------------------------------------------------------------------
// Kernel 1: fp16 HMMA GEMM + fused bias + tanh/v-dot -> raw scores
// Software-pipelined: LDG chunk c+1 overlaps MMA of chunk c.
// grid (16, 256), 256 threads (8 warps, 4x2 warp grid, 32x64 warp tiles)
// ---------------------------------------------------------------------------
__global__ __launch_bounds__(256, 2) void score_kernel(
    const float* __restrict__ st, const float* __restrict__ dy,
    const float* __restrict__ dec, const float* __restrict__ v,
    const float* __restrict__ W, float* __restrict__ out) {
    __shared__ __align__(16) __half2 As16[BM][AS2];
    __shared__ __align__(16) __half2 Bs16[BK / 2][BS2];
    __shared__ float vs[Hq];
    __shared__ float cs[Hq];
    __shared__ float red[4][BN];

    const int b  = blockIdx.y;
    const int n0 = blockIdx.x * BN;
    const int t  = threadIdx.x;
    const int w  = t >> 5;
    const int lane = t & 31;
    const int wm = w & 3;
    const int wn = w >> 2;
    const int gid = lane >> 2;
    const int tig = lane & 3;

    // ---- fused bias: cs[h] = W[h][256:384] . dec[b] ----
    if (t < Hq) {
        vs[t] = v[t];
        red[0][t] = dec[b * Hq + t];
    }
    __syncthreads();
    {
        const float* dsh = &red[0][0];
#pragma unroll
        for (int r = 0; r < 16; r++) {
            const int h = w * 16 + r;
            float p = 0.f;
#pragma unroll
            for (int i = 0; i < 4; i++)
                p = fmaf(W[h * 384 + 256 + lane + 32 * i], dsh[lane + 32 * i], p);
#pragma unroll
            for (int off = 16; off; off >>= 1)
                p += __shfl_xor_sync(0xffffffffu, p, off);
            if (lane == 0) cs[h] = p;
        }
    }

    float acc[2][8][4];
#pragma unroll
    for (int i = 0; i < 2; i++)
#pragma unroll
        for (int j = 0; j < 8; j++)
#pragma unroll
            for (int q = 0; q < 4; q++) acc[i][j][q] = 0.f;

    const float* base_st = st + (size_t)b * Hq * Nq;
    const float* base_dy = dy + (size_t)b * Hq * Nq;

    // loop-invariant loader indices
    // A: slots i=0,1 -> s = t + 256*i; h = s>>2; q = s&3
    const int ah0 = t >> 2,            aq0 = t & 3;
    const int ah1 = (t + 256) >> 2,    aq1 = t & 3;     // (t+256)&3 == t&3
    // B: slots i=0,1 -> k2 = s>>5; c4 = s&31
    const int bk0 = t >> 5,            bc  = t & 31;
    const int bk1 = (t + 256) >> 5;

    float4 pa[2][2], pb[2][2];

    // ---- prologue: LDG chunk 0 ----
    {
        const float* wp0 = &W[ah0 * 384 + aq0 * 8];
        const float* wp1 = &W[ah1 * 384 + aq1 * 8];
        pa[0][0] = *(const float4*)wp0;  pa[0][1] = *(const float4*)(wp0 + 4);
        pa[1][0] = *(const float4*)wp1;  pa[1][1] = *(const float4*)(wp1 + 4);
        const float* s0 = base_st + (size_t)(2 * bk0) * Nq + n0 + bc * 4;
        const float* s1 = base_st + (size_t)(2 * bk1) * Nq + n0 + bc * 4;
        pb[0][0] = *(const float4*)s0;   pb[0][1] = *(const float4*)(s0 + Nq);
        pb[1][0] = *(const float4*)s1;   pb[1][1] = *(const float4*)(s1 + Nq);
    }

    for (int c = 0; c < 8; c++) {
        // ---- pack + STS current registers ----
        {
            uint4 k0, k1;
            k0.x = pack2(pa[0][0].x, pa[0][0].y); k0.y = pack2(pa[0][0].z, pa[0][0].w);
            k0.z = pack2(pa[0][1].x, pa[0][1].y); k0.w = pack2(pa[0][1].z, pa[0][1].w);
            k1.x = pack2(pa[1][0].x, pa[1][0].y); k1.y = pack2(pa[1][0].z, pa[1][0].w);
            k1.z = pack2(pa[1][1].x, pa[1][1].y); k1.w = pack2(pa[1][1].z, pa[1][1].w);
            *(uint4*)&As16[ah0][aq0 * 4] = k0;
            *(uint4*)&As16[ah1][aq1 * 4] = k1;
            uint4 b0, b1;
            b0.x = pack2(pb[0][0].x, pb[0][1].x); b0.y = pack2(pb[0][0].y, pb[0][1].y);
            b0.z = pack2(pb[0][0].z, pb[0][1].z); b0.w = pack2(pb[0][0].w, pb[0][1].w);
            b1.x = pack2(pb[1][0].x, pb[1][1].x); b1.y = pack2(pb[1][0].y, pb[1][1].y);
            b1.z = pack2(pb[1][0].z, pb[1][1].z); b1.w = pack2(pb[1][0].w, pb[1][1].w);
            *(uint4*)&Bs16[bk0][bc * 4] = b0;
            *(uint4*)&Bs16[bk1][bc * 4] = b1;
        }
        __syncthreads();

        // ---- issue LDG for chunk c+1 (latency hides under MMA below) ----
        if (c < 7) {
            const int cn = c + 1;
            const float* wp0 = &W[ah0 * 384 + cn * BK + aq0 * 8];
            const float* wp1 = &W[ah1 * 384 + cn * BK + aq1 * 8];
            pa[0][0] = *(const float4*)wp0;  pa[0][1] = *(const float4*)(wp0 + 4);
            pa[1][0] = *(const float4*)wp1;  pa[1][1] = *(const float4*)(wp1 + 4);
            const int gk0 = cn * BK + 2 * bk0;
            const int gk1 = cn * BK + 2 * bk1;
            const float* s0 = (gk0 < Hq ? base_st + (size_t)gk0 * Nq
                                        : base_dy + (size_t)(gk0 - Hq) * Nq) + n0 + bc * 4;
            const float* s1 = (gk1 < Hq ? base_st + (size_t)gk1 * Nq
                                        : base_dy + (size_t)(gk1 - Hq) * Nq) + n0 + bc * 4;
            pb[0][0] = *(const float4*)s0;   pb[0][1] = *(const float4*)(s0 + Nq);
            pb[1][0] = *(const float4*)s1;   pb[1][1] = *(const float4*)(s1 + Nq);
        }

        // ---- MMA on current smem tiles ----
#pragma unroll
        for (int kf = 0; kf < 2; kf++) {
            const int k2 = kf * 8;
            uint32_t a[2][4], bb[8][2];
#pragma unroll
            for (int mf = 0; mf < 2; mf++) {
                const int m = wm * 32 + mf * 16;
                a[mf][0] = *(const uint32_t*)&As16[m + gid][k2 + tig];
                a[mf][1] = *(const uint32_t*)&As16[m + gid + 8][k2 + tig];
                a[mf][2] = *(const uint32_t*)&As16[m + gid][k2 + tig + 4];
                a[mf][3] = *(const uint32_t*)&As16[m + gid + 8][k2 + tig + 4];
            }
#pragma unroll
            for (int nf = 0; nf < 8; nf++) {
                const int n = wn * 64 + nf * 8;
                bb[nf][0] = *(const uint32_t*)&Bs16[k2 + tig][n + gid];
                bb[nf][1] = *(const uint32_t*)&Bs16[k2 + tig + 4][n + gid];
            }
#pragma unroll
            for (int mf = 0; mf < 2; mf++)
#pragma unroll
                for (int nf = 0; nf < 8; nf++)
                    mma16(acc[mf][nf], a[mf], bb[nf]);
        }
        __syncthreads();
    }

    // ---- epilogue: tanh + v-dot, reduce over m ----
#pragma unroll
    for (int nf = 0; nf < 8; nf++) {
        float p0 = 0.f, p1 = 0.f;
#pragma unroll
        for (int mf = 0; mf < 2; mf++) {
            const int r0 = wm * 32 + mf * 16 + gid;
            const int r1 = r0 + 8;
            const float v0 = vs[r0], c0 = cs[r0];
            const float v1 = vs[r1], c1 = cs[r1];
            p0 = fmaf(v0, tanh_fast(acc[mf][nf][0] + c0), p0);
            p1 = fmaf(v0, tanh_fast(acc[mf][nf][1] + c0), p1);
            p0 = fmaf(v1, tanh_fast(acc[mf][nf][2] + c1), p0);
            p1 = fmaf(v1, tanh_fast(acc[mf][nf][3] + c1), p1);
        }
#pragma unroll
        for (int off = 4; off < 32; off <<= 1) {
            p0 += __shfl_xor_sync(0xffffffffu, p0, off);
            p1 += __shfl_xor_sync(0xffffffffu, p1, off);
        }
        if (gid == 0) {
            const int col = wn * 64 + nf * 8 + 2 * tig;
            red[wm][col]     = p0;
            red[wm][col + 1] = p1;
        }
    }
    __syncthreads();

    if (t < BN)
        out[(size_t)b * Nq + n0 + t] =
            red[0][t] + red[1][t] + red[2][t] + red[3][t];
}

// ---------------------------------------------------------------------------
// Kernel 2: in-place row softmax over N=2048
// ---------------------------------------------------------------------------
__global__ __launch_bounds__(256) void softmax_kernel(float* __restrict__ out) {
    __shared__ float sm[8];
    const int b = blockIdx.x, t = threadIdx.x;
    const int w = t >> 5, lane = t & 31;
    float* row = out + (size_t)b * Nq;

    float vals[8];
    float m = -1e30f;
#pragma unroll
    for (int i = 0; i < 8; i++) { vals[i] = row[t + 256 * i]; m = fmaxf(m, vals[i]); }
#pragma unroll
    for (int off = 16; off; off >>= 1)
        m = fmaxf(m, __shfl_xor_sync(0xffffffffu, m, off));
    if (lane == 0) sm[w] = m;
    __syncthreads();
    float M = sm[lane & 7];
#pragma unroll
    for (int off = 4; off; off >>= 1)
        M = fmaxf(M, __shfl_xor_sync(0xffffffffu, M, off));

    float sum = 0.f;
#pragma unroll
    for (int i = 0; i < 8; i++) { vals[i] = __expf(vals[i] - M); sum += vals[i]; }
#pragma unroll
    for (int off = 16; off; off >>= 1)
        sum += __shfl_xor_sync(0xffffffffu, sum, off);
    __syncthreads();
    if (lane == 0) sm[w] = sum;
    __syncthreads();
    float S = sm[lane & 7];
#pragma unroll
    for (int off = 4; off; off >>= 1)
        S += __shfl_xor_sync(0xffffffffu, S, off);

    const float inv = 1.f / S;
#pragma unroll
    for (int i = 0; i < 8; i++) row[t + 256 * i] = vals[i] * inv;
}

// ---------------------------------------------------------------------------
extern "C" void kernel_launch(void* const* d_in, const int* in_sizes, int n_in,
                              void* d_out, int out_size) {
    const float* st  = (const float*)d_in[0];
    const float* dy  = (const float*)d_in[1];
    const float* dec = (const float*)d_in[2];
    const float* v   = (const float*)d_in[3];
    const float* W   = (const float*)d_in[4];
    float* out = (float*)d_out;

    score_kernel<<<dim3(Nq / BN, Bq), 256>>>(st, dy, dec, v, W, out);
    softmax_kernel<<<Bq, 256>>>(out);
}